// round 13
// baseline (speedup 1.0000x reference)
#include <cuda_runtime.h>
#include <cuda_fp16.h>
#include <cstdint>

#define BATCH 4096
#define MCOLS 4096
#define NROWS 4096
#define NNZ_PER_ROW 819
#define NNZ_TOTAL (NROWS * NNZ_PER_ROW)

#define BM 128
#define BN 128
#define BK 32
#define KSTEPS (MCOLS / BK)        // 128
#define NSTAGES 4
#define SROWH 40                   // halves per row (80B); LDSM phases tile all 32 banks
#define TILE_HALVES (128 * SROWH)  // 10KB per matrix per stage
#define STAGE_HALVES (2 * TILE_HALVES)            // A+B per stage (20KB)
#define SMEM_BYTES (NSTAGES * STAGE_HALVES * 2)   // 81920 B -> 2 CTAs/SM

#define XCHUNKS (BATCH * MCOLS / 4)   // float4 chunks of x

// fp16 operand buffers. g_Wh is zero-initialized at module load (0 bits = +0.0h);
// the prep kernel writes the same values to the same (fixed CSR) positions every
// call -> deterministic across graph replays.
__device__ __half g_Wh[(size_t)NROWS * MCOLS];
__device__ __half g_Xh[(size_t)BATCH * MCOLS];

__global__ void __launch_bounds__(256)
prep_kernel(const float* __restrict__ x, const float* __restrict__ val,
            const int* __restrict__ rows, const int* __restrict__ cols) {
    int i = blockIdx.x * blockDim.x + threadIdx.x;
    if (i < XCHUNKS) {
        size_t o = (size_t)i * 4;
        float4 v = *(const float4*)(x + o);
        __half2 h0 = __floats2half2_rn(v.x, v.y);
        __half2 h1 = __floats2half2_rn(v.z, v.w);
        uint2 p;
        p.x = *(const uint32_t*)&h0;
        p.y = *(const uint32_t*)&h1;
        *(uint2*)(g_Xh + o) = p;
    } else {
        int j = i - XCHUNKS;
        if (j < NNZ_TOTAL) {
            g_Wh[(size_t)rows[j] * MCOLS + cols[j]] = __float2half_rn(val[j]);
        }
    }
}

__device__ __forceinline__ void cp16(uint32_t dst, const void* src) {
    asm volatile("cp.async.cg.shared.global [%0], [%1], 16;\n" :: "r"(dst), "l"(src));
}

// 128-thread loader: thread owns row tid; 4 x 16B chunks per matrix.
__device__ __forceinline__ void load_stage(uint32_t sAt, uint32_t sBt,
                                           const __half* __restrict__ gA,
                                           const __half* __restrict__ gB) {
    #pragma unroll
    for (int i = 0; i < 4; ++i) {
        uint32_t so = (uint32_t)(i * 8) * 2;   // +8 halves (16B) per chunk
        cp16(sAt + so, gA + i * 8);
        cp16(sBt + so, gB + i * 8);
    }
    asm volatile("cp.async.commit_group;\n" ::);
}

#define MMA(d, a0, a1, a2, a3, b0, b1)                                      \
    asm volatile(                                                           \
        "mma.sync.aligned.m16n8k16.row.col.f32.f16.f16.f32 "                \
        "{%0,%1,%2,%3}, {%4,%5,%6,%7}, {%8,%9}, {%0,%1,%2,%3};"             \
        : "+f"((d)[0]), "+f"((d)[1]), "+f"((d)[2]), "+f"((d)[3])            \
        : "r"(a0), "r"(a1), "r"(a2), "r"(a3), "r"(b0), "r"(b1))

#define LDSM4(r0, r1, r2, r3, addr)                                         \
    asm volatile("ldmatrix.sync.aligned.m8n8.x4.shared.b16 "                \
                 "{%0,%1,%2,%3}, [%4];"                                     \
                 : "=r"(r0), "=r"(r1), "=r"(r2), "=r"(r3) : "r"(addr))

// ldmatrix fragment loads for a 64x64 warp tile (4 A + 4 B LDSM.x4 per ks).
__device__ __forceinline__ void load_frags(uint32_t af[4][4], uint32_t bf[8][2],
                                           uint32_t aAddr, uint32_t bAddr, int ks) {
    #pragma unroll
    for (int mt = 0; mt < 4; ++mt)
        LDSM4(af[mt][0], af[mt][1], af[mt][2], af[mt][3],
              aAddr + (uint32_t)((mt * 16 * SROWH + ks * 16) * 2));
    #pragma unroll
    for (int ntp = 0; ntp < 4; ++ntp)
        LDSM4(bf[2 * ntp][0], bf[2 * ntp][1], bf[2 * ntp + 1][0], bf[2 * ntp + 1][1],
              bAddr + (uint32_t)((ntp * 16 * SROWH + ks * 16) * 2));
}

__global__ void __launch_bounds__(128, 2)
sgemm_fp16(const float* __restrict__ bias, float* __restrict__ out) {
    extern __shared__ __half smem[];

    const int tid  = threadIdx.x;
    const int lane = tid & 31;
    const int warp = tid >> 5;          // 0..3
    const int wm = (warp & 1) * 64;     // 2 warps in M
    const int wn = (warp >> 1) * 64;    // 2 warps in N
    const int qr = lane >> 2;
    const int tg = lane & 3;

    const int m0 = blockIdx.y * BM;
    const int n0 = blockIdx.x * BN;

    float acc[4][8][4];
    #pragma unroll
    for (int i = 0; i < 4; i++)
        #pragma unroll
        for (int j = 0; j < 8; j++)
            #pragma unroll
            for (int c = 0; c < 4; c++) acc[i][j][c] = 0.f;

    const uint32_t sbase = (uint32_t)__cvta_generic_to_shared(smem);

    // ldmatrix per-lane source addresses (stage 0; stage offset added in-loop)
    const int lrA = wm + (lane & 7) + ((lane >> 3) & 1) * 8;
    const int lkA = (lane >> 4) * 8;
    const int lrB = wn + (lane & 7) + (lane >> 4) * 8;
    const int lkB = ((lane >> 3) & 1) * 8;
    const uint32_t aFrag0 = sbase + (uint32_t)((lrA * SROWH + lkA) * 2);
    const uint32_t bFrag0 = sbase + (uint32_t)(TILE_HALVES * 2)
                                  + (uint32_t)((lrB * SROWH + lkB) * 2);

    // loader thread's fixed row (one 64B row per matrix)
    const int lrow = tid;               // 0..127
    const uint32_t lA = sbase + (uint32_t)(lrow * SROWH) * 2;
    const uint32_t lB = lA + (uint32_t)(TILE_HALVES * 2);
    const __half* gA = g_Xh + (size_t)(m0 + lrow) * MCOLS;
    const __half* gB = g_Wh + (size_t)(n0 + lrow) * MCOLS;

    // prologue: stages 0,1,2 into buffers 0,1,2
    load_stage(lA, lB, gA, gB);
    load_stage(lA + 1 * STAGE_HALVES * 2, lB + 1 * STAGE_HALVES * 2, gA + BK, gB + BK);
    load_stage(lA + 2 * STAGE_HALVES * 2, lB + 2 * STAGE_HALVES * 2,
               gA + 2 * BK, gB + 2 * BK);

    int cur = 0;   // buffer holding stage kt
    for (int kt = 0; kt < KSTEPS; ++kt) {
        // Pending groups: stages kt+1, kt+2 (when they exist). Allowing 2 pending
        // completes stage kt for all threads; the barrier orders it CTA-wide.
        if (kt + 2 < KSTEPS) {
            asm volatile("cp.async.wait_group 2;\n" ::);
        } else if (kt + 1 < KSTEPS) {
            asm volatile("cp.async.wait_group 1;\n" ::);
        } else {
            asm volatile("cp.async.wait_group 0;\n" ::);
        }
        __syncthreads();   // SINGLE barrier per ktile

        const uint32_t aAddr = aFrag0 + (uint32_t)(cur * STAGE_HALVES * 2);
        const uint32_t bAddr = bFrag0 + (uint32_t)(cur * STAGE_HALVES * 2);

        uint32_t af[2][4][4];
        uint32_t bf[2][8][2];
        load_frags(af[0], bf[0], aAddr, bAddr, 0);

        // Prefetch stage kt+3 into buffer (kt+3)%4 == (kt-1)%4: last read during
        // iteration kt-1, whose compute finished before the barrier above.
        if (kt + 3 < KSTEPS) {
            const int lb = (kt + 3) & (NSTAGES - 1);
            load_stage(lA + (uint32_t)(lb * STAGE_HALVES * 2),
                       lB + (uint32_t)(lb * STAGE_HALVES * 2),
                       gA + (size_t)(kt + 3) * BK, gB + (size_t)(kt + 3) * BK);
        }

        #pragma unroll
        for (int ks = 0; ks < 2; ++ks) {
            const int c = ks & 1;
            if (ks < 1)
                load_frags(af[c ^ 1], bf[c ^ 1], aAddr, bAddr, ks + 1);
            #pragma unroll
            for (int mt = 0; mt < 4; ++mt)
                #pragma unroll
                for (int nt = 0; nt < 8; ++nt)
                    MMA(acc[mt][nt], af[c][mt][0], af[c][mt][1],
                        af[c][mt][2], af[c][mt][3],
                        bf[c][nt][0], bf[c][nt][1]);
        }

        cur = (cur + 1) & (NSTAGES - 1);
    }

    // Epilogue
    #pragma unroll
    for (int mt = 0; mt < 4; ++mt) {
        const int rbase = m0 + wm + mt * 16 + qr;
        #pragma unroll
        for (int nt = 0; nt < 8; ++nt) {
            const int nbase = n0 + wn + nt * 8 + 2 * tg;
            const float b0 = bias[nbase];
            const float b1 = bias[nbase + 1];
            float2 v0 = make_float2(acc[mt][nt][0] + b0, acc[mt][nt][1] + b1);
            float2 v1 = make_float2(acc[mt][nt][2] + b0, acc[mt][nt][3] + b1);
            *(float2*)(out + (size_t)rbase * NROWS + nbase) = v0;
            *(float2*)(out + (size_t)(rbase + 8) * NROWS + nbase) = v1;
        }
    }
}

extern "C" void kernel_launch(void* const* d_in, const int* in_sizes, int n_in,
                              void* d_out, int out_size) {
    const float* x    = (const float*)d_in[0];
    const float* wval = (const float*)d_in[1];
    const float* bias = (const float*)d_in[2];
    const int*   rows = (const int*)d_in[3];
    const int*   cols = (const int*)d_in[4];
    float* out = (float*)d_out;

    prep_kernel<<<(XCHUNKS + NNZ_TOTAL + 255) / 256, 256>>>(x, wval, rows, cols);

    cudaFuncSetAttribute(sgemm_fp16,
                         cudaFuncAttributeMaxDynamicSharedMemorySize, SMEM_BYTES);
    dim3 grid(NROWS / BN, BATCH / BM);
    sgemm_fp16<<<grid, 128, SMEM_BYTES>>>(bias, out);
}

// round 14
// speedup vs baseline: 1.5578x; 1.5578x over previous
#include <cuda_runtime.h>
#include <cuda_fp16.h>
#include <cstdint>

#define BATCH 4096
#define MCOLS 4096
#define NROWS 4096
#define NNZ_PER_ROW 819
#define NNZ_TOTAL (NROWS * NNZ_PER_ROW)

#define BM 128
#define BN 128
#define BK 32
#define KSTEPS (MCOLS / BK)        // 128
#define NSTAGES 4
#define SROWH 40                   // halves per row (80B); LDSM phases tile all 32 banks
#define TILE_HALVES (128 * SROWH)  // 10KB per matrix per stage
#define STAGE_HALVES (2 * TILE_HALVES)            // A+B per stage (20KB)
#define SMEM_BYTES (NSTAGES * STAGE_HALVES * 2)   // 81920 B -> 2 CTAs/SM

#define XCHUNKS (BATCH * MCOLS / 4)   // float4 chunks of x

// fp16 operand buffers. g_Wh is zero-initialized at module load (0 bits = +0.0h);
// the prep kernel writes the same values to the same (fixed CSR) positions every
// call -> deterministic across graph replays.
__device__ __half g_Wh[(size_t)NROWS * MCOLS];
__device__ __half g_Xh[(size_t)BATCH * MCOLS];

__global__ void __launch_bounds__(256)
prep_kernel(const float* __restrict__ x, const float* __restrict__ val,
            const int* __restrict__ rows, const int* __restrict__ cols) {
    int i = blockIdx.x * blockDim.x + threadIdx.x;
    if (i < XCHUNKS) {
        size_t o = (size_t)i * 4;
        float4 v = *(const float4*)(x + o);
        __half2 h0 = __floats2half2_rn(v.x, v.y);
        __half2 h1 = __floats2half2_rn(v.z, v.w);
        uint2 p;
        p.x = *(const uint32_t*)&h0;
        p.y = *(const uint32_t*)&h1;
        *(uint2*)(g_Xh + o) = p;
    } else {
        int j = i - XCHUNKS;
        if (j < NNZ_TOTAL) {
            g_Wh[(size_t)rows[j] * MCOLS + cols[j]] = __float2half_rn(val[j]);
        }
    }
}

__device__ __forceinline__ void cp16(uint32_t dst, const void* src) {
    asm volatile("cp.async.cg.shared.global [%0], [%1], 16;\n" :: "r"(dst), "l"(src));
}

// R12 loader: thread owns (row tid>>2, 16B seg tid&3); 2 chunks per matrix.
__device__ __forceinline__ void load_stage(uint32_t sAt, uint32_t sBt,
                                           const __half* __restrict__ gA,
                                           const __half* __restrict__ gB) {
    #pragma unroll
    for (int i = 0; i < 2; ++i) {
        uint32_t so = (uint32_t)(i * 64 * SROWH) * 2;   // +64 rows per step
        cp16(sAt + so, gA + (size_t)i * 64 * MCOLS);
        cp16(sBt + so, gB + (size_t)i * 64 * MCOLS);
    }
    asm volatile("cp.async.commit_group;\n" ::);
}

#define MMA(d, a0, a1, a2, a3, b0, b1)                                      \
    asm volatile(                                                           \
        "mma.sync.aligned.m16n8k16.row.col.f32.f16.f16.f32 "                \
        "{%0,%1,%2,%3}, {%4,%5,%6,%7}, {%8,%9}, {%0,%1,%2,%3};"             \
        : "+f"((d)[0]), "+f"((d)[1]), "+f"((d)[2]), "+f"((d)[3])            \
        : "r"(a0), "r"(a1), "r"(a2), "r"(a3), "r"(b0), "r"(b1))

#define LDSM4(r0, r1, r2, r3, addr)                                         \
    asm volatile("ldmatrix.sync.aligned.m8n8.x4.shared.b16 "                \
                 "{%0,%1,%2,%3}, [%4];"                                     \
                 : "=r"(r0), "=r"(r1), "=r"(r2), "=r"(r3) : "r"(addr))

// ldmatrix fragment loads (R10/R12 lane mapping).
__device__ __forceinline__ void load_frags(uint32_t af[2][4], uint32_t bf[8][2],
                                           uint32_t aAddr, uint32_t bAddr, int ks) {
    #pragma unroll
    for (int mt = 0; mt < 2; ++mt)
        LDSM4(af[mt][0], af[mt][1], af[mt][2], af[mt][3],
              aAddr + (uint32_t)((mt * 16 * SROWH + ks * 16) * 2));
    #pragma unroll
    for (int ntp = 0; ntp < 4; ++ntp)
        LDSM4(bf[2 * ntp][0], bf[2 * ntp][1], bf[2 * ntp + 1][0], bf[2 * ntp + 1][1],
              bAddr + (uint32_t)((ntp * 16 * SROWH + ks * 16) * 2));
}

__global__ void __launch_bounds__(256, 2)
sgemm_fp16(const float* __restrict__ bias, float* __restrict__ out) {
    extern __shared__ __half smem[];

    const int tid  = threadIdx.x;
    const int lane = tid & 31;
    const int warp = tid >> 5;
    const int wm = (warp & 3) * 32;     // 4 warps in M
    const int wn = (warp >> 2) * 64;    // 2 warps in N
    const int qr = lane >> 2;
    const int tg = lane & 3;

    const int m0 = blockIdx.y * BM;
    const int n0 = blockIdx.x * BN;

    float acc[2][8][4];
    #pragma unroll
    for (int i = 0; i < 2; i++)
        #pragma unroll
        for (int j = 0; j < 8; j++)
            #pragma unroll
            for (int c = 0; c < 4; c++) acc[i][j][c] = 0.f;

    const uint32_t sbase = (uint32_t)__cvta_generic_to_shared(smem);

    // ldmatrix per-lane source addresses (stage 0; stage offset added in-loop)
    const int lrA = wm + (lane & 7) + ((lane >> 3) & 1) * 8;
    const int lkA = (lane >> 4) * 8;
    const int lrB = wn + (lane & 7) + (lane >> 4) * 8;
    const int lkB = ((lane >> 3) & 1) * 8;
    const uint32_t aFrag0 = sbase + (uint32_t)((lrA * SROWH + lkA) * 2);
    const uint32_t bFrag0 = sbase + (uint32_t)(TILE_HALVES * 2)
                                  + (uint32_t)((lrB * SROWH + lkB) * 2);

    // loader thread's fixed (row, seg): 16B chunks
    const int lrow = tid >> 2;          // 0..63
    const int lseg = tid & 3;           // 0..3
    const uint32_t lA = sbase + (uint32_t)(lrow * SROWH + lseg * 8) * 2;
    const uint32_t lB = lA + (uint32_t)(TILE_HALVES * 2);
    const __half* gA = g_Xh + (size_t)(m0 + lrow) * MCOLS + lseg * 8;
    const __half* gB = g_Wh + (size_t)(n0 + lrow) * MCOLS + lseg * 8;

    // prologue: stages 0,1,2 into buffers 0,1,2
    load_stage(lA, lB, gA, gB);
    load_stage(lA + 1 * STAGE_HALVES * 2, lB + 1 * STAGE_HALVES * 2, gA + BK, gB + BK);
    load_stage(lA + 2 * STAGE_HALVES * 2, lB + 2 * STAGE_HALVES * 2,
               gA + 2 * BK, gB + 2 * BK);

    // Stages 0 AND 1 complete + CTA-visible before the loop (pending: stage 2).
    asm volatile("cp.async.wait_group 1;\n" ::);
    __syncthreads();

    uint32_t af[2][2][4];
    uint32_t bf[2][8][2];
    // preload (kt=0, ks=0) fragments
    load_frags(af[0], bf[0], aFrag0, bFrag0, 0);

    for (int kt = 0; kt < KSTEPS; ++kt) {
        const int cur = kt & (NSTAGES - 1);
        const uint32_t aAddr = aFrag0 + (uint32_t)(cur * STAGE_HALVES * 2);
        const uint32_t bAddr = bFrag0 + (uint32_t)(cur * STAGE_HALVES * 2);

        // Prefetch stage kt+3 into buffer (kt+3)&3 == (kt-1)&3. All reads of that
        // buffer (iter kt-1's ks1 frags and its (kt,ks0) preload) completed before
        // the barrier that ended iteration kt-1.
        if (kt + 3 < KSTEPS) {
            const int lb = (kt + 3) & (NSTAGES - 1);
            load_stage(lA + (uint32_t)(lb * STAGE_HALVES * 2),
                       lB + (uint32_t)(lb * STAGE_HALVES * 2),
                       gA + (size_t)(kt + 3) * BK, gB + (size_t)(kt + 3) * BK);
        }

        // ks1 fragments of the current stage
        load_frags(af[1], bf[1], aAddr, bAddr, 1);

        // MMA ks0 (fragments preloaded before the barrier)
        #pragma unroll
        for (int mt = 0; mt < 2; ++mt)
            #pragma unroll
            for (int nt = 0; nt < 8; ++nt)
                MMA(acc[mt][nt], af[0][mt][0], af[0][mt][1],
                    af[0][mt][2], af[0][mt][3], bf[0][nt][0], bf[0][nt][1]);

        // Preload next tile's ks0 fragments from stage kt+1 (buffer (cur+1)&3):
        // completed+visible since the previous wait(<=1)+barrier; not a prefetch
        // target this iteration ((kt+3)&3 != (kt+1)&3).
        if (kt + 1 < KSTEPS)
            load_frags(af[0], bf[0],
                       aFrag0 + (uint32_t)(((kt + 1) & (NSTAGES - 1)) * STAGE_HALVES * 2),
                       bFrag0 + (uint32_t)(((kt + 1) & (NSTAGES - 1)) * STAGE_HALVES * 2),
                       0);

        // MMA ks1
        #pragma unroll
        for (int mt = 0; mt < 2; ++mt)
            #pragma unroll
            for (int nt = 0; nt < 8; ++nt)
                MMA(acc[mt][nt], af[1][mt][0], af[1][mt][1],
                    af[1][mt][2], af[1][mt][3], bf[1][nt][0], bf[1][nt][1]);

        // Complete stage kt+2 (pending: kt+2, kt+3 -> allow 1) so next iteration
        // may preload (kt+2, ks0) after the barrier.
        if (kt + 3 < KSTEPS) {
            asm volatile("cp.async.wait_group 1;\n" ::);
        } else {
            asm volatile("cp.async.wait_group 0;\n" ::);
        }
        __syncthreads();
    }

    // Epilogue
    #pragma unroll
    for (int mt = 0; mt < 2; ++mt) {
        const int rbase = m0 + wm + mt * 16 + qr;
        #pragma unroll
        for (int nt = 0; nt < 8; ++nt) {
            const int nbase = n0 + wn + nt * 8 + 2 * tg;
            const float b0 = bias[nbase];
            const float b1 = bias[nbase + 1];
            float2 v0 = make_float2(acc[mt][nt][0] + b0, acc[mt][nt][1] + b1);
            float2 v1 = make_float2(acc[mt][nt][2] + b0, acc[mt][nt][3] + b1);
            *(float2*)(out + (size_t)rbase * NROWS + nbase) = v0;
            *(float2*)(out + (size_t)(rbase + 8) * NROWS + nbase) = v1;
        }
    }
}

extern "C" void kernel_launch(void* const* d_in, const int* in_sizes, int n_in,
                              void* d_out, int out_size) {
    const float* x    = (const float*)d_in[0];
    const float* wval = (const float*)d_in[1];
    const float* bias = (const float*)d_in[2];
    const int*   rows = (const int*)d_in[3];
    const int*   cols = (const int*)d_in[4];
    float* out = (float*)d_out;

    prep_kernel<<<(XCHUNKS + NNZ_TOTAL + 255) / 256, 256>>>(x, wval, rows, cols);

    cudaFuncSetAttribute(sgemm_fp16,
                         cudaFuncAttributeMaxDynamicSharedMemorySize, SMEM_BYTES);
    dim3 grid(NROWS / BN, BATCH / BM);
    sgemm_fp16<<<grid, 256, SMEM_BYTES>>>(bias, out);
}

// round 15
// speedup vs baseline: 1.6317x; 1.0474x over previous
#include <cuda_runtime.h>
#include <cuda_fp16.h>
#include <cstdint>

#define BATCH 4096
#define MCOLS 4096
#define NROWS 4096
#define NNZ_PER_ROW 819
#define NNZ_TOTAL (NROWS * NNZ_PER_ROW)

#define BM 128
#define BN 128
#define BK 32
#define KSTEPS (MCOLS / BK)        // 128
#define NSTAGES 4
#define SROWH 40                   // halves per row (80B); LDSM phases tile all 32 banks
#define TILE_HALVES (128 * SROWH)  // 10KB per matrix per stage
#define STAGE_HALVES (2 * TILE_HALVES)            // A+B per stage (20KB)
#define SMEM_BYTES (NSTAGES * STAGE_HALVES * 2)   // 81920 B -> 2 CTAs/SM

#define XCHUNKS (BATCH * MCOLS / 4)   // float4 chunks of x

// fp16 operand buffers. g_Wh is zero-initialized at module load (0 bits = +0.0h);
// the prep kernel writes the same values to the same (fixed CSR) positions every
// call -> deterministic across graph replays.
__device__ __half g_Wh[(size_t)NROWS * MCOLS];
__device__ __half g_Xh[(size_t)BATCH * MCOLS];

__global__ void __launch_bounds__(256)
prep_kernel(const float* __restrict__ x, const float* __restrict__ val,
            const int* __restrict__ rows, const int* __restrict__ cols) {
    int i = blockIdx.x * blockDim.x + threadIdx.x;
    if (i < XCHUNKS) {
        size_t o = (size_t)i * 4;
        float4 v = *(const float4*)(x + o);
        __half2 h0 = __floats2half2_rn(v.x, v.y);
        __half2 h1 = __floats2half2_rn(v.z, v.w);
        uint2 p;
        p.x = *(const uint32_t*)&h0;
        p.y = *(const uint32_t*)&h1;
        *(uint2*)(g_Xh + o) = p;
    } else {
        int j = i - XCHUNKS;
        if (j < NNZ_TOTAL) {
            g_Wh[(size_t)rows[j] * MCOLS + cols[j]] = __float2half_rn(val[j]);
        }
    }
}

__device__ __forceinline__ void cp16(uint32_t dst, const void* src) {
    asm volatile("cp.async.cg.shared.global [%0], [%1], 16;\n" :: "r"(dst), "l"(src));
}

// Loader: thread owns (row tid>>2, 16B seg tid&3); 2 chunks per matrix.
__device__ __forceinline__ void load_stage(uint32_t sAt, uint32_t sBt,
                                           const __half* __restrict__ gA,
                                           const __half* __restrict__ gB) {
    #pragma unroll
    for (int i = 0; i < 2; ++i) {
        uint32_t so = (uint32_t)(i * 64 * SROWH) * 2;   // +64 rows per step
        cp16(sAt + so, gA + (size_t)i * 64 * MCOLS);
        cp16(sBt + so, gB + (size_t)i * 64 * MCOLS);
    }
    asm volatile("cp.async.commit_group;\n" ::);
}

#define MMA(d, a0, a1, a2, a3, b0, b1)                                      \
    asm volatile(                                                           \
        "mma.sync.aligned.m16n8k16.row.col.f32.f16.f16.f32 "                \
        "{%0,%1,%2,%3}, {%4,%5,%6,%7}, {%8,%9}, {%0,%1,%2,%3};"             \
        : "+f"((d)[0]), "+f"((d)[1]), "+f"((d)[2]), "+f"((d)[3])            \
        : "r"(a0), "r"(a1), "r"(a2), "r"(a3), "r"(b0), "r"(b1))

#define LDSM4(r0, r1, r2, r3, addr)                                         \
    asm volatile("ldmatrix.sync.aligned.m8n8.x4.shared.b16 "                \
                 "{%0,%1,%2,%3}, [%4];"                                     \
                 : "=r"(r0), "=r"(r1), "=r"(r2), "=r"(r3) : "r"(addr))

// ldmatrix fragment loads (R10/R12 lane mapping).
__device__ __forceinline__ void load_frags(uint32_t af[2][4], uint32_t bf[8][2],
                                           uint32_t aAddr, uint32_t bAddr, int ks) {
    #pragma unroll
    for (int mt = 0; mt < 2; ++mt)
        LDSM4(af[mt][0], af[mt][1], af[mt][2], af[mt][3],
              aAddr + (uint32_t)((mt * 16 * SROWH + ks * 16) * 2));
    #pragma unroll
    for (int ntp = 0; ntp < 4; ++ntp)
        LDSM4(bf[2 * ntp][0], bf[2 * ntp][1], bf[2 * ntp + 1][0], bf[2 * ntp + 1][1],
              bAddr + (uint32_t)((ntp * 16 * SROWH + ks * 16) * 2));
}

__global__ void __launch_bounds__(256, 2)
sgemm_fp16(const float* __restrict__ bias, float* __restrict__ out) {
    extern __shared__ __half smem[];

    const int tid  = threadIdx.x;
    const int lane = tid & 31;
    const int warp = tid >> 5;
    const int wm = (warp & 3) * 32;     // 4 warps in M
    const int wn = (warp >> 2) * 64;    // 2 warps in N
    const int qr = lane >> 2;
    const int tg = lane & 3;

    const int m0 = blockIdx.y * BM;
    const int n0 = blockIdx.x * BN;

    float acc[2][8][4];
    #pragma unroll
    for (int i = 0; i < 2; i++)
        #pragma unroll
        for (int j = 0; j < 8; j++)
            #pragma unroll
            for (int c = 0; c < 4; c++) acc[i][j][c] = 0.f;

    const uint32_t sbase = (uint32_t)__cvta_generic_to_shared(smem);

    // ldmatrix per-lane source addresses (stage 0; stage offset added in-loop)
    const int lrA = wm + (lane & 7) + ((lane >> 3) & 1) * 8;
    const int lkA = (lane >> 4) * 8;
    const int lrB = wn + (lane & 7) + (lane >> 4) * 8;
    const int lkB = ((lane >> 3) & 1) * 8;
    const uint32_t aFrag0 = sbase + (uint32_t)((lrA * SROWH + lkA) * 2);
    const uint32_t bFrag0 = sbase + (uint32_t)(TILE_HALVES * 2)
                                  + (uint32_t)((lrB * SROWH + lkB) * 2);

    // loader thread's fixed (row, seg): 16B chunks
    const int lrow = tid >> 2;          // 0..63
    const int lseg = tid & 3;           // 0..3
    const uint32_t lA = sbase + (uint32_t)(lrow * SROWH + lseg * 8) * 2;
    const uint32_t lB = lA + (uint32_t)(TILE_HALVES * 2);
    const __half* gA = g_Xh + (size_t)(m0 + lrow) * MCOLS + lseg * 8;
    const __half* gB = g_Wh + (size_t)(n0 + lrow) * MCOLS + lseg * 8;

    // prologue: stages 0,1,2 into buffers 0,1,2
    load_stage(lA, lB, gA, gB);
    load_stage(lA + 1 * STAGE_HALVES * 2, lB + 1 * STAGE_HALVES * 2, gA + BK, gB + BK);
    load_stage(lA + 2 * STAGE_HALVES * 2, lB + 2 * STAGE_HALVES * 2,
               gA + 2 * BK, gB + 2 * BK);

    // Stages 0 AND 1 complete + CTA-visible before the loop (pending: stage 2).
    asm volatile("cp.async.wait_group 1;\n" ::);
    __syncthreads();

    uint32_t af[2][2][4];
    uint32_t bf[2][8][2];
    // preload (kt=0, ks=0) fragments
    load_frags(af[0], bf[0], aFrag0, bFrag0, 0);

    for (int kt = 0; kt < KSTEPS; ++kt) {
        const int cur = kt & (NSTAGES - 1);
        const uint32_t aAddr = aFrag0 + (uint32_t)(cur * STAGE_HALVES * 2);
        const uint32_t bAddr = bFrag0 + (uint32_t)(cur * STAGE_HALVES * 2);

        // 1) MMA ks0 FIRST (operands preloaded before the barrier): the tensor
        //    pipe is busy from the first post-barrier cycle.
        #pragma unroll
        for (int mt = 0; mt < 2; ++mt)
            #pragma unroll
            for (int nt = 0; nt < 8; ++nt)
                MMA(acc[mt][nt], af[0][mt][0], af[0][mt][1],
                    af[0][mt][2], af[0][mt][3], bf[0][nt][0], bf[0][nt][1]);

        // 2) ks1 fragments — issue under ks0's tensor execution; LDSM latency
        //    completes well before the ks0 MMA drain.
        load_frags(af[1], bf[1], aAddr, bAddr, 1);

        // 3) Prefetch stage kt+3 into buffer (kt+3)&3 == (kt-1)&3 (least urgent
        //    LSU work: ~2 iterations of slack). That buffer's reads finished
        //    before the barrier that ended iteration kt-1.
        if (kt + 3 < KSTEPS) {
            const int lb = (kt + 3) & (NSTAGES - 1);
            load_stage(lA + (uint32_t)(lb * STAGE_HALVES * 2),
                       lB + (uint32_t)(lb * STAGE_HALVES * 2),
                       gA + (size_t)(kt + 3) * BK, gB + (size_t)(kt + 3) * BK);
        }

        // 4) Preload next tile's ks0 fragments from stage kt+1 (buffer (cur+1)&3):
        //    completed + visible since the previous wait(<=1)+barrier; not a
        //    prefetch target this iteration ((kt+3)&3 != (kt+1)&3).
        if (kt + 1 < KSTEPS)
            load_frags(af[0], bf[0],
                       aFrag0 + (uint32_t)(((kt + 1) & (NSTAGES - 1)) * STAGE_HALVES * 2),
                       bFrag0 + (uint32_t)(((kt + 1) & (NSTAGES - 1)) * STAGE_HALVES * 2),
                       0);

        // 5) MMA ks1
        #pragma unroll
        for (int mt = 0; mt < 2; ++mt)
            #pragma unroll
            for (int nt = 0; nt < 8; ++nt)
                MMA(acc[mt][nt], af[1][mt][0], af[1][mt][1],
                    af[1][mt][2], af[1][mt][3], bf[1][nt][0], bf[1][nt][1]);

        // 6) Complete stage kt+2 (pending kt+2, kt+3 -> allow 1) so the next
        //    iteration may preload (kt+2, ks0) after the barrier.
        if (kt + 3 < KSTEPS) {
            asm volatile("cp.async.wait_group 1;\n" ::);
        } else {
            asm volatile("cp.async.wait_group 0;\n" ::);
        }
        __syncthreads();
    }

    // Epilogue
    #pragma unroll
    for (int mt = 0; mt < 2; ++mt) {
        const int rbase = m0 + wm + mt * 16 + qr;
        #pragma unroll
        for (int nt = 0; nt < 8; ++nt) {
            const int nbase = n0 + wn + nt * 8 + 2 * tg;
            const float b0 = bias[nbase];
            const float b1 = bias[nbase + 1];
            float2 v0 = make_float2(acc[mt][nt][0] + b0, acc[mt][nt][1] + b1);
            float2 v1 = make_float2(acc[mt][nt][2] + b0, acc[mt][nt][3] + b1);
            *(float2*)(out + (size_t)rbase * NROWS + nbase) = v0;
            *(float2*)(out + (size_t)(rbase + 8) * NROWS + nbase) = v1;
        }
    }
}

extern "C" void kernel_launch(void* const* d_in, const int* in_sizes, int n_in,
                              void* d_out, int out_size) {
    const float* x    = (const float*)d_in[0];
    const float* wval = (const float*)d_in[1];
    const float* bias = (const float*)d_in[2];
    const int*   rows = (const int*)d_in[3];
    const int*   cols = (const int*)d_in[4];
    float* out = (float*)d_out;

    prep_kernel<<<(XCHUNKS + NNZ_TOTAL + 255) / 256, 256>>>(x, wval, rows, cols);

    cudaFuncSetAttribute(sgemm_fp16,
                         cudaFuncAttributeMaxDynamicSharedMemorySize, SMEM_BYTES);
    dim3 grid(NROWS / BN, BATCH / BM);
    sgemm_fp16<<<grid, 256, SMEM_BYTES>>>(bias, out);
}

// round 16
// speedup vs baseline: 1.7583x; 1.0776x over previous
#include <cuda_runtime.h>
#include <cuda_fp16.h>
#include <cstdint>

#define BATCH 4096
#define MCOLS 4096
#define NROWS 4096
#define NNZ_PER_ROW 819
#define NNZ_TOTAL (NROWS * NNZ_PER_ROW)

#define BM 128
#define BN 128
#define BK 32
#define KSTEPS (MCOLS / BK)        // 128 ktiles -> 64 two-ktile steps
#define NSTAGES 6
#define TILE_BYTES 8192            // 128 rows x 64B (32 halves), swizzled, no padding
#define STAGE_BYTES (2 * TILE_BYTES)             // A+B (16KB)
#define SMEM_BYTES (NSTAGES * STAGE_BYTES)       // 98304 B -> 2 CTAs/SM

#define XCHUNKS (BATCH * MCOLS / 4)   // float4 chunks of x

// fp16 operand buffers. g_Wh is zero-initialized at module load (0 bits = +0.0h);
// the prep kernel writes the same values to the same (fixed CSR) positions every
// call -> deterministic across graph replays.
__device__ __half g_Wh[(size_t)NROWS * MCOLS];
__device__ __half g_Xh[(size_t)BATCH * MCOLS];

__global__ void __launch_bounds__(256)
prep_kernel(const float* __restrict__ x, const float* __restrict__ val,
            const int* __restrict__ rows, const int* __restrict__ cols) {
    int i = blockIdx.x * blockDim.x + threadIdx.x;
    if (i < XCHUNKS) {
        size_t o = (size_t)i * 4;
        float4 v = *(const float4*)(x + o);
        __half2 h0 = __floats2half2_rn(v.x, v.y);
        __half2 h1 = __floats2half2_rn(v.z, v.w);
        uint2 p;
        p.x = *(const uint32_t*)&h0;
        p.y = *(const uint32_t*)&h1;
        *(uint2*)(g_Xh + o) = p;
    } else {
        int j = i - XCHUNKS;
        if (j < NNZ_TOTAL) {
            g_Wh[(size_t)rows[j] * MCOLS + cols[j]] = __float2half_rn(val[j]);
        }
    }
}

__device__ __forceinline__ void cp16(uint32_t dst, const void* src) {
    asm volatile("cp.async.cg.shared.global [%0], [%1], 16;\n" :: "r"(dst), "l"(src));
}

// Swizzled stage loader. Thread owns (row tid>>1, 32B half-row tid&1) = chunks
// c0, c0+1 per matrix. w0/w1 are the precomputed swizzled smem offsets for those
// chunks (relative to smem base, stage 0, A tile); B tile sits +TILE_BYTES.
__device__ __forceinline__ void load_stage(uint32_t w0, uint32_t w1, uint32_t so,
                                           const __half* __restrict__ gA,
                                           const __half* __restrict__ gB) {
    cp16(w0 + so, gA);
    cp16(w1 + so, gA + 8);
    cp16(w0 + so + TILE_BYTES, gB);
    cp16(w1 + so + TILE_BYTES, gB + 8);
    asm volatile("cp.async.commit_group;\n" ::);
}

#define MMA(d, a0, a1, a2, a3, b0, b1)                                      \
    asm volatile(                                                           \
        "mma.sync.aligned.m16n8k16.row.col.f32.f16.f16.f32 "                \
        "{%0,%1,%2,%3}, {%4,%5,%6,%7}, {%8,%9}, {%0,%1,%2,%3};"             \
        : "+f"((d)[0]), "+f"((d)[1]), "+f"((d)[2]), "+f"((d)[3])            \
        : "r"(a0), "r"(a1), "r"(a2), "r"(a3), "r"(b0), "r"(b1))

#define LDSM4(r0, r1, r2, r3, addr)                                         \
    asm volatile("ldmatrix.sync.aligned.m8n8.x4.shared.b16 "                \
                 "{%0,%1,%2,%3}, [%4];"                                     \
                 : "=r"(r0), "=r"(r1), "=r"(r2), "=r"(r3) : "r"(addr))

// ldmatrix fragment loads, swizzled: per-lane row bases (aLane/bLane, include
// smem base + row*64, and bLane includes +TILE_BYTES) plus per-ks swizzled
// chunk offsets offA/offB (= ((ks*2 + chunksel) ^ q) * 16).
__device__ __forceinline__ void load_frags(uint32_t af[2][4], uint32_t bf[8][2],
                                           uint32_t aBase, uint32_t bBase,
                                           uint32_t offA, uint32_t offB) {
    #pragma unroll
    for (int mt = 0; mt < 2; ++mt)
        LDSM4(af[mt][0], af[mt][1], af[mt][2], af[mt][3],
              aBase + (uint32_t)(mt * 1024) + offA);
    #pragma unroll
    for (int ntp = 0; ntp < 4; ++ntp)
        LDSM4(bf[2 * ntp][0], bf[2 * ntp][1], bf[2 * ntp + 1][0], bf[2 * ntp + 1][1],
              bBase + (uint32_t)(ntp * 1024) + offB);
}

__device__ __forceinline__ uint32_t wrap6(uint32_t so) {
    return (so >= (uint32_t)SMEM_BYTES) ? so - (uint32_t)SMEM_BYTES : so;
}

__global__ void __launch_bounds__(256, 2)
sgemm_fp16(const float* __restrict__ bias, float* __restrict__ out) {
    extern __shared__ __half smem[];

    const int tid  = threadIdx.x;
    const int lane = tid & 31;
    const int warp = tid >> 5;
    const int wm = (warp & 3) * 32;     // 4 warps in M
    const int wn = (warp >> 2) * 64;    // 2 warps in N
    const int qr = lane >> 2;
    const int tg = lane & 3;

    const int m0 = blockIdx.y * BM;
    const int n0 = blockIdx.x * BN;

    float acc[2][8][4];
    #pragma unroll
    for (int i = 0; i < 2; i++)
        #pragma unroll
        for (int j = 0; j < 8; j++)
            #pragma unroll
            for (int c = 0; c < 4; c++) acc[i][j][c] = 0.f;

    const uint32_t sbase = (uint32_t)__cvta_generic_to_shared(smem);

    // ldmatrix per-lane bases + swizzled chunk offsets
    const int rA = wm + (lane & 7) + ((lane >> 3) & 1) * 8;   // + mt*16 in-loop
    const int clA = lane >> 4;                                 // chunk select (k high/low)
    const int rB = wn + (lane & 7) + ((lane >> 4) & 1) * 8;   // + ntp*16 in-loop
    const int clB = (lane >> 3) & 1;
    const uint32_t qA = (uint32_t)((rA >> 1) & 3);             // invariant under +16
    const uint32_t qB = (uint32_t)((rB >> 1) & 3);
    const uint32_t aLane = sbase + (uint32_t)(rA * 64);
    const uint32_t bLane = sbase + (uint32_t)TILE_BYTES + (uint32_t)(rB * 64);
    const uint32_t offA0 = (((uint32_t)clA ^ qA) << 4);            // ks0
    const uint32_t offA1 = (((uint32_t)(2 + clA) ^ qA) << 4);      // ks1
    const uint32_t offB0 = (((uint32_t)clB ^ qB) << 4);
    const uint32_t offB1 = (((uint32_t)(2 + clB) ^ qB) << 4);

    // loader thread's (row, half-row) and swizzled write offsets
    const int lrow = tid >> 1;          // 0..127
    const int lh = tid & 1;             // chunks 2*lh, 2*lh+1
    const uint32_t lq = (uint32_t)((lrow >> 1) & 3);
    const uint32_t w0 = sbase + (uint32_t)(lrow * 64)
                      + ((((uint32_t)(2 * lh)) ^ lq) << 4);
    const uint32_t w1 = sbase + (uint32_t)(lrow * 64)
                      + ((((uint32_t)(2 * lh + 1)) ^ lq) << 4);
    const __half* gA = g_Xh + (size_t)(m0 + lrow) * MCOLS + lh * 16;
    const __half* gB = g_Wh + (size_t)(n0 + lrow) * MCOLS + lh * 16;

    // prologue: stages 0..3; complete 0,1,2 (pending: 3)
    load_stage(w0, w1, 0 * STAGE_BYTES, gA, gB);
    load_stage(w0, w1, 1 * STAGE_BYTES, gA + BK, gB + BK);
    load_stage(w0, w1, 2 * STAGE_BYTES, gA + 2 * BK, gB + 2 * BK);
    load_stage(w0, w1, 3 * STAGE_BYTES, gA + 3 * BK, gB + 3 * BK);
    asm volatile("cp.async.wait_group 1;\n" ::);
    __syncthreads();

    uint32_t af[2][2][4];
    uint32_t bf[2][8][2];
    // one-time preload (ktile 0, ks0)
    load_frags(af[0], bf[0], aLane, bLane, offA0, offB0);

    uint32_t sb0 = 0;   // byte offset of the stage holding ktile e
    for (int s = 0; s < KSTEPS / 2; ++s) {
        const int e = 2 * s;
        const uint32_t s0 = sb0;
        const uint32_t s1 = wrap6(sb0 + STAGE_BYTES);
        const uint32_t s4 = wrap6(sb0 + 4 * STAGE_BYTES);
        const uint32_t s5 = wrap6(sb0 + 5 * STAGE_BYTES);

        // ktile e, ks0 (preloaded pre-barrier)
        #pragma unroll
        for (int mt = 0; mt < 2; ++mt)
            #pragma unroll
            for (int nt = 0; nt < 8; ++nt)
                MMA(acc[mt][nt], af[0][mt][0], af[0][mt][1],
                    af[0][mt][2], af[0][mt][3], bf[0][nt][0], bf[0][nt][1]);

        load_frags(af[1], bf[1], aLane + s0, bLane + s0, offA1, offB1);

        // prefetch stage e+4 into buffer (e+4)%6 == (e-2)%6, fully read in the
        // previous step (before the barrier that started this step).
        if (e + 4 < KSTEPS)
            load_stage(w0, w1, s4, gA + (size_t)(e + 4) * BK, gB + (size_t)(e + 4) * BK);

        // ktile e, ks1
        #pragma unroll
        for (int mt = 0; mt < 2; ++mt)
            #pragma unroll
            for (int nt = 0; nt < 8; ++nt)
                MMA(acc[mt][nt], af[1][mt][0], af[1][mt][1],
                    af[1][mt][2], af[1][mt][3], bf[1][nt][0], bf[1][nt][1]);

        load_frags(af[0], bf[0], aLane + s1, bLane + s1, offA0, offB0);

        // prefetch stage e+5 into buffer (e+5)%6 == (e-1)%6 (read in prev step).
        if (e + 5 < KSTEPS)
            load_stage(w0, w1, s5, gA + (size_t)(e + 5) * BK, gB + (size_t)(e + 5) * BK);

        // ktile e+1, ks0
        #pragma unroll
        for (int mt = 0; mt < 2; ++mt)
            #pragma unroll
            for (int nt = 0; nt < 8; ++nt)
                MMA(acc[mt][nt], af[0][mt][0], af[0][mt][1],
                    af[0][mt][2], af[0][mt][3], bf[0][nt][0], bf[0][nt][1]);

        load_frags(af[1], bf[1], aLane + s1, bLane + s1, offA1, offB1);

        // ktile e+1, ks1
        #pragma unroll
        for (int mt = 0; mt < 2; ++mt)
            #pragma unroll
            for (int nt = 0; nt < 8; ++nt)
                MMA(acc[mt][nt], af[1][mt][0], af[1][mt][1],
                    af[1][mt][2], af[1][mt][3], bf[1][nt][0], bf[1][nt][1]);

        // Complete stages e+3, e+4 (leave e+5 pending) so the next step's
        // entry invariant holds: stages e', e'+1, e'+2 complete, e'+3 pending.
        if (e + 5 < KSTEPS) {
            asm volatile("cp.async.wait_group 1;\n" ::);
        } else {
            asm volatile("cp.async.wait_group 0;\n" ::);
        }

        // pre-barrier preload of (ktile e+2, ks0) from stage e+2 (complete since
        // this step's entry barrier; its buffer is not a prefetch target here).
        if (e + 2 < KSTEPS) {
            const uint32_t s2 = wrap6(sb0 + 2 * STAGE_BYTES);
            load_frags(af[0], bf[0], aLane + s2, bLane + s2, offA0, offB0);
        }

        __syncthreads();
        sb0 = wrap6(sb0 + 2 * STAGE_BYTES);
    }

    // Epilogue
    #pragma unroll
    for (int mt = 0; mt < 2; ++mt) {
        const int rbase = m0 + wm + mt * 16 + qr;
        #pragma unroll
        for (int nt = 0; nt < 8; ++nt) {
            const int nbase = n0 + wn + nt * 8 + 2 * tg;
            const float b0 = bias[nbase];
            const float b1 = bias[nbase + 1];
            float2 v0 = make_float2(acc[mt][nt][0] + b0, acc[mt][nt][1] + b1);
            float2 v1 = make_float2(acc[mt][nt][2] + b0, acc[mt][nt][3] + b1);
            *(float2*)(out + (size_t)rbase * NROWS + nbase) = v0;
            *(float2*)(out + (size_t)(rbase + 8) * NROWS + nbase) = v1;
        }
    }
}

extern "C" void kernel_launch(void* const* d_in, const int* in_sizes, int n_in,
                              void* d_out, int out_size) {
    const float* x    = (const float*)d_in[0];
    const float* wval = (const float*)d_in[1];
    const float* bias = (const float*)d_in[2];
    const int*   rows = (const int*)d_in[3];
    const int*   cols = (const int*)d_in[4];
    float* out = (float*)d_out;

    prep_kernel<<<(XCHUNKS + NNZ_TOTAL + 255) / 256, 256>>>(x, wval, rows, cols);

    cudaFuncSetAttribute(sgemm_fp16,
                         cudaFuncAttributeMaxDynamicSharedMemorySize, SMEM_BYTES);
    dim3 grid(NROWS / BN, BATCH / BM);
    sgemm_fp16<<<grid, 256, SMEM_BYTES>>>(bias, out);
}